// round 5
// baseline (speedup 1.0000x reference)
#include <cuda_runtime.h>

#define N_NODES 100000
#define N_EDGES 1600000
#define NFEAT   48
#define HIDDEN  256
#define TILE    128   // nodes per block in k_node

// Scratch (no allocation allowed -> __device__ globals)
__device__ float g_w[NFEAT];     // fused W1@W2
__device__ float g_c;            // fused bias term
__device__ float g_deg[N_NODES]; // degree (incl. self loop)
__device__ float g_dinv[N_NODES];
__device__ float g_z[N_NODES];   // (x[i] . w) * dinv[i]

// ---- 1. fused: all blocks init deg=1; block 0 also computes w, c ----
__global__ void k_pre(const float* __restrict__ W1,
                      const float* __restrict__ bias,
                      const float* __restrict__ W2,
                      const float* __restrict__ b2) {
    int i = blockIdx.x * blockDim.x + threadIdx.x;
    if (i < N_NODES) g_deg[i] = 1.0f;

    if (blockIdx.x == 0) {
        __shared__ float s_w2[HIDDEN];
        int t = threadIdx.x;            // blockDim == HIDDEN == 256
        s_w2[t] = W2[t];
        __syncthreads();
        if (t < NFEAT) {
            const float* r = W1 + t * HIDDEN;
            float acc = 0.f;
#pragma unroll 8
            for (int h = 0; h < HIDDEN; ++h) acc = fmaf(r[h], s_w2[h], acc);
            g_w[t] = acc;
        }
        if (t == 0) {
            float s = 0.f;
            for (int h = 0; h < HIDDEN; ++h) s += s_w2[h];
            g_c = bias[0] * s + b2[0];
        }
    }
}

// ---- 2. degree count, 4 edges per thread (int4) ----
__global__ void k_count(const int* __restrict__ ei) {
    int t = blockIdx.x * blockDim.x + threadIdx.x;
    if (t < N_EDGES / 4) {
        const int4* cols = reinterpret_cast<const int4*>(ei + N_EDGES);
        int4 c = __ldg(&cols[t]);
        atomicAdd(&g_deg[c.x], 1.0f);
        atomicAdd(&g_deg[c.y], 1.0f);
        atomicAdd(&g_deg[c.z], 1.0f);
        atomicAdd(&g_deg[c.w], 1.0f);
    }
}

// ---- 3. per-node dot product, coalesced via smem tile ----
__global__ void __launch_bounds__(TILE) k_node(const float* __restrict__ x,
                                               float* __restrict__ out) {
    __shared__ float sx[TILE * 49];   // stride-49 padding: conflict-free reads
    __shared__ float sw[NFEAT];

    int t    = threadIdx.x;
    int tile = blockIdx.x * TILE;
    int nn   = min(TILE, N_NODES - tile);

    if (t < NFEAT) sw[t] = g_w[t];

    // Stage tile coalesced: contiguous float4 stream -> padded smem
    const float4* src = reinterpret_cast<const float4*>(x + (size_t)tile * NFEAT);
    int nf4 = nn * (NFEAT / 4);                 // float4 count in this tile
    for (int idx = t; idx < nf4; idx += TILE) {
        float4 v  = __ldg(&src[idx]);
        int node  = idx / 12;
        int f4    = idx - node * 12;
        float* d  = &sx[node * 49 + f4 * 4];
        d[0] = v.x; d[1] = v.y; d[2] = v.z; d[3] = v.w;
    }
    __syncthreads();

    if (t < nn) {
        int i = tile + t;
        float dinv = rsqrtf(g_deg[i]);          // deg >= 1 always
        const float* r = &sx[t * 49];
        float a0 = 0.f, a1 = 0.f, a2 = 0.f, a3 = 0.f;
#pragma unroll
        for (int k = 0; k < NFEAT; k += 4) {
            a0 = fmaf(r[k + 0], sw[k + 0], a0);
            a1 = fmaf(r[k + 1], sw[k + 1], a1);
            a2 = fmaf(r[k + 2], sw[k + 2], a2);
            a3 = fmaf(r[k + 3], sw[k + 3], a3);
        }
        float z = ((a0 + a1) + (a2 + a3)) * dinv;
        g_dinv[i] = dinv;
        g_z[i]    = z;
        out[i]    = z;   // self-loop term; second dinv applied in finalize
    }
}

// ---- 4. scatter: out[col] += z[row], 4 edges per thread ----
__global__ void k_scatter(const int* __restrict__ ei, float* __restrict__ out) {
    int t = blockIdx.x * blockDim.x + threadIdx.x;
    if (t < N_EDGES / 4) {
        const int4* rows = reinterpret_cast<const int4*>(ei);
        const int4* cols = reinterpret_cast<const int4*>(ei + N_EDGES);
        int4 r = __ldg(&rows[t]);
        int4 c = __ldg(&cols[t]);
        float z0 = __ldg(&g_z[r.x]);
        float z1 = __ldg(&g_z[r.y]);
        float z2 = __ldg(&g_z[r.z]);
        float z3 = __ldg(&g_z[r.w]);
        atomicAdd(&out[c.x], z0);
        atomicAdd(&out[c.y], z1);
        atomicAdd(&out[c.z], z2);
        atomicAdd(&out[c.w], z3);
    }
}

// ---- 5. finalize: out = out*dinv + c (vectorized) ----
__global__ void k_final(float* __restrict__ out) {
    int t = blockIdx.x * blockDim.x + threadIdx.x;
    float4* o4 = reinterpret_cast<float4*>(out);
    const float4* d4 = reinterpret_cast<const float4*>(g_dinv);
    if (t < N_NODES / 4) {
        float4 o = o4[t];
        float4 d = d4[t];
        float  c = g_c;
        o.x = fmaf(o.x, d.x, c);
        o.y = fmaf(o.y, d.y, c);
        o.z = fmaf(o.z, d.z, c);
        o.w = fmaf(o.w, d.w, c);
        o4[t] = o;
    }
}

extern "C" void kernel_launch(void* const* d_in, const int* in_sizes, int n_in,
                              void* d_out, int out_size) {
    const float* x    = (const float*)d_in[0];
    const int*   ei   = (const int*)  d_in[1];
    const float* W1   = (const float*)d_in[2];
    const float* bias = (const float*)d_in[3];
    const float* W2   = (const float*)d_in[4];
    const float* b2   = (const float*)d_in[5];
    float* out = (float*)d_out;

    const int TB = 256;
    const int nb_pre  = (N_NODES + TB - 1) / TB;           // 391
    const int nb_e4   = (N_EDGES / 4 + TB - 1) / TB;       // 1563
    const int nb_node = (N_NODES + TILE - 1) / TILE;       // 782
    const int nb_fin  = (N_NODES / 4 + TB - 1) / TB;       // 98  (100000 % 4 == 0)

    k_pre    <<<nb_pre,  TB>>>(W1, bias, W2, b2);
    k_count  <<<nb_e4,   TB>>>(ei);
    k_node   <<<nb_node, TILE>>>(x, out);
    k_scatter<<<nb_e4,   TB>>>(ei, out);
    k_final  <<<nb_fin,  TB>>>(out);
}

// round 7
// speedup vs baseline: 1.0362x; 1.0362x over previous
#include <cuda_runtime.h>

#define N_NODES 100000
#define N_EDGES 1600000
#define NFEAT   48
#define HIDDEN  256
#define TILE    128   // nodes per block in k_dot

// Scratch (no device allocation allowed -> __device__ globals)
__device__ float g_w[NFEAT];     // fused W1@W2
__device__ float g_c;            // fused bias term
__device__ float g_deg[N_NODES]; // degree (incl. self loop)
__device__ float g_dinv[N_NODES];
__device__ float g_z[N_NODES];   // first y = x.w, then z = y*dinv (in place)

// ---- stream A1: fuse weights: w = W1@W2, c = bias*sum(W2)+b2 ----
__global__ void k_fuse_w(const float* __restrict__ W1,
                         const float* __restrict__ bias,
                         const float* __restrict__ W2,
                         const float* __restrict__ b2) {
    __shared__ float s_w2[HIDDEN];
    int t = threadIdx.x;              // blockDim == HIDDEN == 256
    s_w2[t] = W2[t];
    __syncthreads();
    if (t < NFEAT) {
        const float* r = W1 + t * HIDDEN;
        float acc = 0.f;
#pragma unroll 8
        for (int h = 0; h < HIDDEN; ++h) acc = fmaf(r[h], s_w2[h], acc);
        g_w[t] = acc;
    }
    if (t == 0) {
        float s = 0.f;
        for (int h = 0; h < HIDDEN; ++h) s += s_w2[h];
        g_c = bias[0] * s + b2[0];
    }
}

// ---- stream A2: y[i] = x[i].w  (coalesced via padded smem tile) ----
__global__ void __launch_bounds__(TILE) k_dot(const float* __restrict__ x) {
    __shared__ float sx[TILE * 49];   // stride-49 padding: conflict-free reads
    __shared__ float sw[NFEAT];

    int t    = threadIdx.x;
    int tile = blockIdx.x * TILE;
    int nn   = min(TILE, N_NODES - tile);

    if (t < NFEAT) sw[t] = g_w[t];

    const float4* src = reinterpret_cast<const float4*>(x + (size_t)tile * NFEAT);
    int nf4 = nn * (NFEAT / 4);
    for (int idx = t; idx < nf4; idx += TILE) {
        float4 v = __ldg(&src[idx]);
        int node = idx / 12;
        int f4   = idx - node * 12;
        float* d = &sx[node * 49 + f4 * 4];
        d[0] = v.x; d[1] = v.y; d[2] = v.z; d[3] = v.w;
    }
    __syncthreads();

    if (t < nn) {
        const float* r = &sx[t * 49];
        float a0 = 0.f, a1 = 0.f, a2 = 0.f, a3 = 0.f;
#pragma unroll
        for (int k = 0; k < NFEAT; k += 4) {
            a0 = fmaf(r[k + 0], sw[k + 0], a0);
            a1 = fmaf(r[k + 1], sw[k + 1], a1);
            a2 = fmaf(r[k + 2], sw[k + 2], a2);
            a3 = fmaf(r[k + 3], sw[k + 3], a3);
        }
        g_z[tile + t] = (a0 + a1) + (a2 + a3);   // y (dinv applied later)
    }
}

// ---- stream B1: init degree = 1 (self loop) ----
__global__ void k_init_deg() {
    int t = blockIdx.x * blockDim.x + threadIdx.x;
    if (t < N_NODES / 4) {
        reinterpret_cast<float4*>(g_deg)[t] = make_float4(1.f, 1.f, 1.f, 1.f);
    }
}

// ---- stream B2: degree count, 8 edges per thread ----
__global__ void k_count(const int* __restrict__ ei) {
    int t = blockIdx.x * blockDim.x + threadIdx.x;
    if (t < N_EDGES / 8) {
        const int4* cols = reinterpret_cast<const int4*>(ei + N_EDGES);
        int4 c0 = __ldg(&cols[2 * t]);
        int4 c1 = __ldg(&cols[2 * t + 1]);
        atomicAdd(&g_deg[c0.x], 1.0f);
        atomicAdd(&g_deg[c0.y], 1.0f);
        atomicAdd(&g_deg[c0.z], 1.0f);
        atomicAdd(&g_deg[c0.w], 1.0f);
        atomicAdd(&g_deg[c1.x], 1.0f);
        atomicAdd(&g_deg[c1.y], 1.0f);
        atomicAdd(&g_deg[c1.z], 1.0f);
        atomicAdd(&g_deg[c1.w], 1.0f);
    }
}

// ---- join: z = y * rsqrt(deg); out = z; store dinv ----
__global__ void k_z(float* __restrict__ out) {
    int t = blockIdx.x * blockDim.x + threadIdx.x;
    if (t < N_NODES / 4) {   // 100000 % 4 == 0
        float4 y = reinterpret_cast<const float4*>(g_z)[t];
        float4 d = reinterpret_cast<const float4*>(g_deg)[t];
        float4 di = make_float4(rsqrtf(d.x), rsqrtf(d.y), rsqrtf(d.z), rsqrtf(d.w));
        float4 z = make_float4(y.x * di.x, y.y * di.y, y.z * di.z, y.w * di.w);
        reinterpret_cast<float4*>(g_dinv)[t] = di;
        reinterpret_cast<float4*>(g_z)[t]    = z;
        reinterpret_cast<float4*>(out)[t]    = z;   // self-loop term
    }
}

// ---- scatter: out[col] += z[row], 8 edges per thread ----
__global__ void k_scatter(const int* __restrict__ ei, float* __restrict__ out) {
    int t = blockIdx.x * blockDim.x + threadIdx.x;
    if (t < N_EDGES / 8) {
        const int4* rows = reinterpret_cast<const int4*>(ei);
        const int4* cols = reinterpret_cast<const int4*>(ei + N_EDGES);
        int4 r0 = __ldg(&rows[2 * t]);
        int4 r1 = __ldg(&rows[2 * t + 1]);
        int4 c0 = __ldg(&cols[2 * t]);
        int4 c1 = __ldg(&cols[2 * t + 1]);
        float z0 = __ldg(&g_z[r0.x]);
        float z1 = __ldg(&g_z[r0.y]);
        float z2 = __ldg(&g_z[r0.z]);
        float z3 = __ldg(&g_z[r0.w]);
        float z4 = __ldg(&g_z[r1.x]);
        float z5 = __ldg(&g_z[r1.y]);
        float z6 = __ldg(&g_z[r1.z]);
        float z7 = __ldg(&g_z[r1.w]);
        atomicAdd(&out[c0.x], z0);
        atomicAdd(&out[c0.y], z1);
        atomicAdd(&out[c0.z], z2);
        atomicAdd(&out[c0.w], z3);
        atomicAdd(&out[c1.x], z4);
        atomicAdd(&out[c1.y], z5);
        atomicAdd(&out[c1.z], z6);
        atomicAdd(&out[c1.w], z7);
    }
}

// ---- finalize: out = out*dinv + c (vectorized) ----
__global__ void k_final(float* __restrict__ out) {
    int t = blockIdx.x * blockDim.x + threadIdx.x;
    if (t < N_NODES / 4) {
        float4 o = reinterpret_cast<const float4*>(out)[t];
        float4 d = reinterpret_cast<const float4*>(g_dinv)[t];
        float  c = g_c;
        o.x = fmaf(o.x, d.x, c);
        o.y = fmaf(o.y, d.y, c);
        o.z = fmaf(o.z, d.z, c);
        o.w = fmaf(o.w, d.w, c);
        reinterpret_cast<float4*>(out)[t] = o;
    }
}

extern "C" void kernel_launch(void* const* d_in, const int* in_sizes, int n_in,
                              void* d_out, int out_size) {
    const float* x    = (const float*)d_in[0];
    const int*   ei   = (const int*)  d_in[1];
    const float* W1   = (const float*)d_in[2];
    const float* bias = (const float*)d_in[3];
    const float* W2   = (const float*)d_in[4];
    const float* b2   = (const float*)d_in[5];
    float* out = (float*)d_out;

    const int TB = 256;
    const int nb_n4   = (N_NODES / 4 + TB - 1) / TB;   // 98
    const int nb_e8   = (N_EDGES / 8 + TB - 1) / TB;   // 782
    const int nb_node = (N_NODES + TILE - 1) / TILE;   // 782

    // Fork a side stream so the (fuse_w -> dot) DRAM-bound chain overlaps the
    // (init_deg -> count) atomic/LSU-bound chain. Host-side stream/event
    // creation only (no device memory). Leaked intentionally: kernel_launch is
    // invoked a bounded number of times (correctness + capture).
    cudaStream_t s1;
    cudaEvent_t  eFork, eJoin;
    cudaStreamCreateWithFlags(&s1, cudaStreamNonBlocking);
    cudaEventCreateWithFlags(&eFork, cudaEventDisableTiming);
    cudaEventCreateWithFlags(&eJoin, cudaEventDisableTiming);

    cudaEventRecord(eFork, 0);            // fork point on captured stream
    cudaStreamWaitEvent(s1, eFork, 0);

    // side stream: weights then dense dot product
    k_fuse_w<<<1, HIDDEN, 0, s1>>>(W1, bias, W2, b2);
    k_dot   <<<nb_node, TILE, 0, s1>>>(x);
    cudaEventRecord(eJoin, s1);

    // main stream: degree chain (overlaps with side stream)
    k_init_deg<<<nb_n4, TB>>>();
    k_count   <<<nb_e8, TB>>>(ei);

    cudaStreamWaitEvent(0, eJoin, 0);     // join

    k_z      <<<nb_n4, TB>>>(out);
    k_scatter<<<nb_e8, TB>>>(ei, out);
    k_final  <<<nb_n4, TB>>>(out);
}